// round 10
// baseline (speedup 1.0000x reference)
#include <cuda_runtime.h>
#include <math.h>

#define H 1024
#define W 1024
#define HW (H*W)
#define NSX 19          // ceil(1024/56)
#define SH  16          // strip height
#define NSY (H/SH)      // 64
#define SPP (NSX*NSY)   // strips per image-pair = 1216
#define NT 256
#define WPB (NT/32)

typedef unsigned long long u64;

__device__ int g_count = 0;
__device__ int g_ticket = 0;

__device__ __forceinline__ u64 pk(float lo, float hi) {
    u64 r; asm("mov.b64 %0,{%1,%2};" : "=l"(r) : "f"(lo), "f"(hi)); return r;
}
__device__ __forceinline__ void upk(u64 v, float& lo, float& hi) {
    asm("mov.b64 {%0,%1},%2;" : "=f"(lo), "=f"(hi) : "l"(v));
}
__device__ __forceinline__ u64 fadd2(u64 a, u64 b) {
    u64 r; asm("add.rn.f32x2 %0,%1,%2;" : "=l"(r) : "l"(a), "l"(b)); return r;
}
__device__ __forceinline__ u64 fmul2(u64 a, u64 b) {
    u64 r; asm("mul.rn.f32x2 %0,%1,%2;" : "=l"(r) : "l"(a), "l"(b)); return r;
}
__device__ __forceinline__ u64 ffma2(u64 a, u64 b, u64 c) {
    u64 r; asm("fma.rn.f32x2 %0,%1,%2,%3;" : "=l"(r) : "l"(a), "l"(b), "l"(c)); return r;
}
__device__ __forceinline__ u64 fneg2(u64 a) { return a ^ 0x8000000080000000ULL; }
__device__ __forceinline__ u64 fsub2(u64 a, u64 b) { return fadd2(a, fneg2(b)); }

__device__ __forceinline__ int reflecti(int c, int n) {
    if (c < 0) c = -c;
    if (c >= n) c = 2*n - 2 - c;
    return c;
}

#define GW0 0.05448868454964294f
#define GW1 0.24420134723186663f
#define GW2 0.4026199364369709f
#define T_LO 0.41421356237309503f
#define T_HI 2.414213562373095f
#define TH2  0.009999f

__device__ __forceinline__ int ax_code(float gx, float gy) {
    float axv = fabsf(gx), ayv = fabsf(gy);
    if (ayv <= T_LO * axv) return 0;                                   // H axis
    if (ayv >= T_HI * axv) return 1;                                   // V axis
    return ((__float_as_int(gx) ^ __float_as_int(gy)) >= 0) ? 2 : 3;   // diagonals
}

__device__ __forceinline__ u64 tap5(u64 t0, u64 t1, u64 t2, u64 t3, u64 t4,
                                    u64 K0, u64 K1, u64 K2) {
    u64 acc = fmul2(fadd2(t0, t4), K0);
    acc = ffma2(fadd2(t1, t3), K1, acc);
    return ffma2(t2, K2, acc);
}

__device__ __forceinline__ bool nms1(float c, float L, float R, float U, float D,
                                     float UL, float UR, float DL, float DR, int code) {
    float n1 = (code == 0) ? L : (code == 1) ? U : (code == 2) ? UR : UL;
    float n2 = (code == 0) ? R : (code == 1) ? D : (code == 2) ? DL : DR;
    return (c > n1) & (c > n2) & (c > TH2);
}

__global__ __launch_bounds__(NT)
void edge_loss_kernel(const float* __restrict__ op, const float* __restrict__ gt,
                      float* __restrict__ out, float inv_n, int total_warps)
{
    const int lane = threadIdx.x & 31;
    const int w = blockIdx.x * WPB + (threadIdx.x >> 5);
    if (w >= total_warps) return;

    const int n  = w / SPP;
    const int s  = w - n * SPP;
    const int sy = s / NSX;
    const int sx = s - sy * NSX;
    const int xb = sx * 56 - 4;
    const int ys = sy * SH;

    const float* __restrict__ po = op + (size_t)n * 3 * HW;
    const float* __restrict__ pg = gt + (size_t)n * 3 * HW;

    const bool xedge = (sx == 0) || (sx == NSX - 1);
    const int  c0  = xb + 2 * lane;
    const int  rc0 = reflecti(c0, W), rc1 = reflecti(c0 + 1, W);
    const bool vlane = (lane >= 2) && (lane <= 29);
    const bool v0 = vlane && ((unsigned)c0 < W);
    const bool v1 = vlane && ((unsigned)(c0 + 1) < W);
    const bool lok = (c0 - 1 >= 0);
    const bool rok = (c0 + 2 <= W - 1);
    const bool x0ok = ((unsigned)c0 < W);
    const bool x1ok = ((unsigned)(c0 + 1) < W);

    const u64 K0c = pk(GW0, GW0);
    const u64 K1c = pk(GW1, GW1);
    const u64 K2c = pk(GW2, GW2);

    u64 h0[2], h1[2], h2[2], h3[2], h4[2];
    u64 va[2], vb_[2], vc[2];
    u64 m0[2], m1[2], m2[2];
    unsigned codes1 = 0, codes2 = 0;
    m0[0]=m0[1]=m1[0]=m1[1]=m2[0]=m2[1]=0ULL;

    u64 g[2];
    #define LOADGRAY(gr, gdst) do {                                               \
        int yy_ = reflecti((gr), H);                                              \
        const float* ro_ = po + yy_ * W;                                          \
        const float* rg_ = pg + yy_ * W;                                          \
        float ao0_, ao1_, ag0_, ag1_;                                             \
        if (!xedge) {                                                             \
            float2 r_o = *(const float2*)(ro_ + c0);                              \
            float2 g_o = *(const float2*)(ro_ + HW + c0);                         \
            float2 b_o = *(const float2*)(ro_ + 2*HW + c0);                       \
            float2 r_g = *(const float2*)(rg_ + c0);                              \
            float2 g_g = *(const float2*)(rg_ + HW + c0);                         \
            float2 b_g = *(const float2*)(rg_ + 2*HW + c0);                       \
            ao0_ = fmaf(0.299f, r_o.x, fmaf(0.587f, g_o.x, 0.114f*b_o.x));        \
            ao1_ = fmaf(0.299f, r_o.y, fmaf(0.587f, g_o.y, 0.114f*b_o.y));        \
            ag0_ = fmaf(0.299f, r_g.x, fmaf(0.587f, g_g.x, 0.114f*b_g.x));        \
            ag1_ = fmaf(0.299f, r_g.y, fmaf(0.587f, g_g.y, 0.114f*b_g.y));        \
        } else {                                                                  \
            ao0_ = fmaf(0.299f, ro_[rc0], fmaf(0.587f, ro_[HW+rc0], 0.114f*ro_[2*HW+rc0])); \
            ao1_ = fmaf(0.299f, ro_[rc1], fmaf(0.587f, ro_[HW+rc1], 0.114f*ro_[2*HW+rc1])); \
            ag0_ = fmaf(0.299f, rg_[rc0], fmaf(0.587f, rg_[HW+rc0], 0.114f*rg_[2*HW+rc0])); \
            ag1_ = fmaf(0.299f, rg_[rc1], fmaf(0.587f, rg_[HW+rc1], 0.114f*rg_[2*HW+rc1])); \
        }                                                                         \
        (gdst)[0] = pk(ao0_, ag0_);                                               \
        (gdst)[1] = pk(ao1_, ag1_);                                               \
    } while (0)

    #define HBLUR(gsrc, hdst) do {                                                \
        u64 gm0_ = __shfl_up_sync(0xffffffffu, (gsrc)[0], 1);                     \
        u64 gm1_ = __shfl_up_sync(0xffffffffu, (gsrc)[1], 1);                     \
        u64 gp0_ = __shfl_down_sync(0xffffffffu, (gsrc)[0], 1);                   \
        u64 gp1_ = __shfl_down_sync(0xffffffffu, (gsrc)[1], 1);                   \
        (hdst)[0] = tap5(gm0_, gm1_, (gsrc)[0], (gsrc)[1], gp0_, K0c, K1c, K2c);  \
        (hdst)[1] = tap5(gm1_, (gsrc)[0], (gsrc)[1], gp0_, gp1_, K0c, K1c, K2c);  \
    } while (0)

    #define HSHIFT_LOAD(row) do {                                                \
        h0[0]=h1[0]; h0[1]=h1[1]; h1[0]=h2[0]; h1[1]=h2[1];                       \
        h2[0]=h3[0]; h2[1]=h3[1]; h3[0]=h4[0]; h3[1]=h4[1];                       \
        LOADGRAY((row), g); HBLUR(g, h4);                                         \
    } while (0)

    #define VTAP(vdst) do {                                                      \
        (vdst)[0] = tap5(h0[0], h1[0], h2[0], h3[0], h4[0], K0c, K1c, K2c);       \
        (vdst)[1] = tap5(h0[1], h1[1], h2[1], h3[1], h4[1], K0c, K1c, K2c);       \
    } while (0)

    int cy = ys - 2; if (cy < 0) cy = 0;
    LOADGRAY(cy - 2, g); HBLUR(g, h0);
    LOADGRAY(cy - 1, g); HBLUR(g, h1);
    LOADGRAY(cy + 0, g); HBLUR(g, h2);
    LOADGRAY(cy + 1, g); HBLUR(g, h3);
    LOADGRAY(cy + 2, g); HBLUR(g, h4);
    u64 vbv[2];
    VTAP(vbv);
    va[0] = vbv[0]; va[1] = vbv[1];         // SV(ys-2)
    {   // SV(ys-1)
        int cyn = min(ys - 1, H - 1);
        if (cyn > cy) { HSHIFT_LOAD(cyn + 2); cy = cyn; VTAP(vbv); }
        vb_[0] = vbv[0]; vb_[1] = vbv[1];
    }

    const u64 TWO = pk(2.0f, 2.0f);
    int cnt = 0;

    // --- main loop: kv = ys .. ys+SH+1 ---
    for (int kv = ys; kv <= ys + SH + 1; kv++) {
        int cyn = min(kv, H - 1);
        if (cyn > cy) { HSHIFT_LOAD(cyn + 2); cy = cyn; VTAP(vbv); }
        vc[0] = vbv[0]; vc[1] = vbv[1];     // SV(kv)

        m0[0]=m1[0]; m0[1]=m1[1]; m1[0]=m2[0]; m1[1]=m2[1];
        codes1 = codes2;

        int m = kv - 1;
        if ((unsigned)m < H) {
            u64 aL = __shfl_up_sync(0xffffffffu, va[1], 1);
            u64 aR = __shfl_down_sync(0xffffffffu, va[0], 1);
            u64 bL = __shfl_up_sync(0xffffffffu, vb_[1], 1);
            u64 bR = __shfl_down_sync(0xffffffffu, vb_[0], 1);
            u64 cL = __shfl_up_sync(0xffffffffu, vc[1], 1);
            u64 cR = __shfl_down_sync(0xffffffffu, vc[0], 1);
            if (!lok) { aL = va[0]; bL = vb_[0]; cL = vc[0]; }
            if (!rok) { aR = va[1]; bR = vb_[1]; cR = vc[1]; }

            u64 gx0 = ffma2(fsub2(vb_[1], bL), TWO, fadd2(fsub2(va[1], aL), fsub2(vc[1], cL)));
            u64 gy0 = ffma2(fsub2(vc[0], va[0]), TWO, fadd2(fsub2(cL, aL), fsub2(vc[1], va[1])));
            u64 gx1 = ffma2(fsub2(bR, vb_[0]), TWO, fadd2(fsub2(aR, va[0]), fsub2(cR, vc[0])));
            u64 gy1 = ffma2(fsub2(vc[1], va[1]), TWO, fadd2(fsub2(vc[0], va[0]), fsub2(cR, aR)));

            u64 q0 = ffma2(gx0, gx0, fmul2(gy0, gy0));
            u64 q1 = ffma2(gx1, gx1, fmul2(gy1, gy1));
            m2[0] = x0ok ? q0 : 0ULL;
            m2[1] = x1ok ? q1 : 0ULL;

            float a, b, c, d;
            upk(gx0, a, b); upk(gy0, c, d);
            unsigned cc = (unsigned)ax_code(a, c) | ((unsigned)ax_code(b, d) << 2);
            upk(gx1, a, b); upk(gy1, c, d);
            cc |= ((unsigned)ax_code(a, c) << 4) | ((unsigned)ax_code(b, d) << 6);
            codes2 = cc;
        } else {
            m2[0] = 0ULL; m2[1] = 0ULL; codes2 = 0;
        }

        if (kv >= ys + 2) {
            u64 L0 = __shfl_up_sync(0xffffffffu, m0[1], 1);
            u64 R0 = __shfl_down_sync(0xffffffffu, m0[0], 1);
            u64 L1 = __shfl_up_sync(0xffffffffu, m1[1], 1);
            u64 R1 = __shfl_down_sync(0xffffffffu, m1[0], 1);
            u64 L2 = __shfl_up_sync(0xffffffffu, m2[1], 1);
            u64 R2 = __shfl_down_sync(0xffffffffu, m2[0], 1);

            float cl, ch, Ll, Lh, Rl, Rh, Ul, Uh, Dl, Dh;
            float ULl, ULh, URl, URh, DLl, DLh, DRl, DRh;

            upk(m1[0], cl, ch); upk(L1, Ll, Lh); upk(m1[1], Rl, Rh);
            upk(m0[0], Ul, Uh); upk(m2[0], Dl, Dh);
            upk(L0, ULl, ULh);  upk(m0[1], URl, URh);
            upk(L2, DLl, DLh);  upk(m2[1], DRl, DRh);
            {
                bool eo = nms1(cl, Ll, Rl, Ul, Dl, ULl, URl, DLl, DRl, (int)(codes1 & 3u));
                bool eg = nms1(ch, Lh, Rh, Uh, Dh, ULh, URh, DLh, DRh, (int)((codes1 >> 2) & 3u));
                cnt += (int)((eo != eg) & v0);
            }
            upk(m1[1], cl, ch); upk(m1[0], Ll, Lh); upk(R1, Rl, Rh);
            upk(m0[1], Ul, Uh); upk(m2[1], Dl, Dh);
            upk(m0[0], ULl, ULh); upk(R0, URl, URh);
            upk(m2[0], DLl, DLh); upk(R2, DRl, DRh);
            {
                bool eo = nms1(cl, Ll, Rl, Ul, Dl, ULl, URl, DLl, DRl, (int)((codes1 >> 4) & 3u));
                bool eg = nms1(ch, Lh, Rh, Uh, Dh, ULh, URh, DLh, DRh, (int)((codes1 >> 6) & 3u));
                cnt += (int)((eo != eg) & v1);
            }
        }

        va[0] = vb_[0]; va[1] = vb_[1];
        vb_[0] = vc[0]; vb_[1] = vc[1];
    }

    #pragma unroll
    for (int o = 16; o > 0; o >>= 1)
        cnt += __shfl_down_sync(0xffffffffu, cnt, o);
    if (lane == 0) {
        atomicAdd(&g_count, cnt);
        __threadfence();
        int t = atomicAdd(&g_ticket, 1);
        if (t == total_warps - 1) {
            out[0] = (float)atomicAdd(&g_count, 0) * inv_n;
            g_count = 0;
            g_ticket = 0;
        }
    }
}

extern "C" void kernel_launch(void* const* d_in, const int* in_sizes, int n_in,
                              void* d_out, int out_size)
{
    const float* op = (const float*)d_in[0];
    const float* gt = (const float*)d_in[1];
    float* out = (float*)d_out;

    int batch = in_sizes[0] / (3 * HW);
    int total_warps = batch * SPP;
    int blocks = (total_warps + WPB - 1) / WPB;
    float inv_n = 1.0f / ((float)batch * HW);

    edge_loss_kernel<<<blocks, NT>>>(op, gt, out, inv_n, total_warps);
}

// round 11
// speedup vs baseline: 1.3021x; 1.3021x over previous
#include <cuda_runtime.h>
#include <math.h>

#define H 1024
#define W 1024
#define HW (H*W)
#define TX 64
#define TY 32
#define SGX 72
#define SGY 40
#define SBX 68
#define SBY 36
#define SMX 66
#define SMY 34
#define NT 512

typedef unsigned long long u64;

__device__ int g_count = 0;
__device__ int g_ticket = 0;

__device__ __forceinline__ u64 pk(float lo, float hi) {
    u64 r; asm("mov.b64 %0,{%1,%2};" : "=l"(r) : "f"(lo), "f"(hi)); return r;
}
__device__ __forceinline__ void upk(u64 v, float& lo, float& hi) {
    asm("mov.b64 {%0,%1},%2;" : "=f"(lo), "=f"(hi) : "l"(v));
}
__device__ __forceinline__ u64 fadd2(u64 a, u64 b) {
    u64 r; asm("add.rn.f32x2 %0,%1,%2;" : "=l"(r) : "l"(a), "l"(b)); return r;
}
__device__ __forceinline__ u64 fmul2(u64 a, u64 b) {
    u64 r; asm("mul.rn.f32x2 %0,%1,%2;" : "=l"(r) : "l"(a), "l"(b)); return r;
}
__device__ __forceinline__ u64 ffma2(u64 a, u64 b, u64 c) {
    u64 r; asm("fma.rn.f32x2 %0,%1,%2,%3;" : "=l"(r) : "l"(a), "l"(b), "l"(c)); return r;
}
__device__ __forceinline__ u64 fneg2(u64 a) { return a ^ 0x8000000080000000ULL; }
__device__ __forceinline__ u64 fsub2(u64 a, u64 b) { return fadd2(a, fneg2(b)); }

__device__ __forceinline__ int reflecti(int c, int n) {
    if (c < 0) c = -c;
    if (c >= n) c = 2*n - 2 - c;
    return c;
}

#define GW0 0.05448868454964294f
#define GW1 0.24420134723186663f
#define GW2 0.4026199364369709f
#define T_LO 0.41421356237309503f
#define T_HI 2.414213562373095f
#define TH2  0.009999f

__device__ __forceinline__ int axis_off(float gx, float gy) {
    float ax = fabsf(gx), ay = fabsf(gy);
    if (ay <= T_LO * ax) return 1;
    if (ay >= T_HI * ax) return SMX;
    return ((__float_as_int(gx) ^ __float_as_int(gy)) >= 0) ? (SMX - 1) : (SMX + 1);
}

__device__ __forceinline__ u64 tap5(u64 t0, u64 t1, u64 t2, u64 t3, u64 t4,
                                    u64 K0, u64 K1, u64 K2) {
    u64 acc = fmul2(fadd2(t0, t4), K0);
    acc = ffma2(fadd2(t1, t3), K1, acc);
    return ffma2(t2, K2, acc);
}

__global__ __launch_bounds__(NT, 4)
void edge_loss_kernel(const float* __restrict__ op, const float* __restrict__ gt,
                      float* __restrict__ out, float inv_n)
{
    __shared__ u64   sA[SGY * SGX];
    __shared__ u64   sB[SGY * SBX];
    __shared__ short snoff[TY * TX];
    __shared__ int   wsum[NT / 32];

    const int tid = threadIdx.x;
    const int x0 = blockIdx.x * TX;
    const int y0 = blockIdx.y * TY;
    const size_t ib = (size_t)blockIdx.z * 3 * HW;
    const float* __restrict__ opi = op + ib;
    const float* __restrict__ gti = gt + ib;

    const u64 K0 = pk(GW0, GW0), K1 = pk(GW1, GW1), K2 = pk(GW2, GW2);
    const u64 TWO = pk(2.0f, 2.0f);

    // ---- Stage 1: grayscale pairs (reflect halo 4) -> sA[SGY][SGX] ----
    #pragma unroll 1
    for (int g = tid; g < SGY * 36; g += NT) {
        int i = g / 36, q = g - i * 36;
        int xlo = x0 - 4 + q * 2;
        if ((unsigned)xlo <= (unsigned)(W - 2)) {
            int yy = reflecti(y0 - 4 + i, H);
            const float* po = opi + yy * W + xlo;
            const float* pg = gti + yy * W + xlo;
            float2 ro = *(const float2*)(po);
            float2 go = *(const float2*)(po + HW);
            float2 bo = *(const float2*)(po + 2 * HW);
            float2 rg = *(const float2*)(pg);
            float2 gg = *(const float2*)(pg + HW);
            float2 bg = *(const float2*)(pg + 2 * HW);
            float o0 = fmaf(0.299f, ro.x, fmaf(0.587f, go.x, 0.114f * bo.x));
            float o1 = fmaf(0.299f, ro.y, fmaf(0.587f, go.y, 0.114f * bo.y));
            float t0 = fmaf(0.299f, rg.x, fmaf(0.587f, gg.x, 0.114f * bg.x));
            float t1 = fmaf(0.299f, rg.y, fmaf(0.587f, gg.y, 0.114f * bg.y));
            *(ulonglong2*)&sA[i * SGX + q * 2] = make_ulonglong2(pk(o0, t0), pk(o1, t1));
        }
    }
    __syncthreads();

    // ---- Stage 1 patch: x-border reflect copies ----
    if (x0 == 0) {
        #pragma unroll 1
        for (int e = tid; e < SGY * 4; e += NT) {
            int r = e >> 2, j = e & 3;
            sA[r * SGX + j] = sA[r * SGX + (8 - j)];
        }
        __syncthreads();
    } else if (x0 == W - TX) {
        #pragma unroll 1
        for (int e = tid; e < SGY * 4; e += NT) {
            int r = e >> 2, j = 68 + (e & 3);
            sA[r * SGX + j] = sA[r * SGX + (134 - j)];
        }
        __syncthreads();
    }

    // ---- Stage 2: hblur 2-wide -> sB[SGY][SBX] ----
    #pragma unroll 1
    for (int s = tid; s < SGY * 34; s += NT) {
        int i = s / 34;
        int j2 = (s - i * 34) << 1;
        const ulonglong2* rv = (const ulonglong2*)&sA[i * SGX + j2];
        ulonglong2 p0 = rv[0], p1 = rv[1], p2 = rv[2];
        u64 o0 = tap5(p0.x, p0.y, p1.x, p1.y, p2.x, K0, K1, K2);
        u64 o1 = tap5(p0.y, p1.x, p1.y, p2.x, p2.y, K0, K1, K2);
        *(ulonglong2*)&sB[i * SBX + j2] = make_ulonglong2(o0, o1);
    }
    __syncthreads();

    // ---- Stage 2 patch: x edge-clamp of blurred field ----
    if (x0 == 0) {
        #pragma unroll 1
        for (int r = tid; r < SGY; r += NT) {
            u64 v = sB[r * SBX + 2];
            sB[r * SBX + 0] = v;
            sB[r * SBX + 1] = v;
        }
        __syncthreads();
    } else if (x0 == W - TX) {
        #pragma unroll 1
        for (int r = tid; r < SGY; r += NT) {
            u64 v = sB[r * SBX + 65];
            sB[r * SBX + 66] = v;
            sB[r * SBX + 67] = v;
        }
        __syncthreads();
    }

    // ---- Stage 3: vblur 2-tall x 1-wide (low reg pressure) -> sA[SBY][SBX] ----
    #pragma unroll 1
    for (int s = tid; s < 18 * SBX; s += NT) {
        int rg = s / SBX;
        int j = s - rg * SBX;
        int r0 = rg << 1;
        const u64* col = &sB[r0 * SBX + j];
        u64 t0 = col[0],       t1 = col[SBX],   t2 = col[2*SBX];
        u64 t3 = col[3*SBX],   t4 = col[4*SBX], t5 = col[5*SBX];
        sA[(r0 + 0) * SBX + j] = tap5(t0, t1, t2, t3, t4, K0, K1, K2);
        sA[(r0 + 1) * SBX + j] = tap5(t1, t2, t3, t4, t5, K0, K1, K2);
    }
    __syncthreads();

    // ---- Stage 3 patch: y edge-clamp of blurred field ----
    if (y0 == 0) {
        #pragma unroll 1
        for (int j = tid; j < SBX; j += NT) {
            u64 v = sA[2 * SBX + j];
            sA[0 * SBX + j] = v;
            sA[1 * SBX + j] = v;
        }
        __syncthreads();
    } else if (y0 == H - TY) {
        #pragma unroll 1
        for (int j = tid; j < SBX; j += NT) {
            u64 v = sA[33 * SBX + j];
            sA[34 * SBX + j] = v;
            sA[35 * SBX + j] = v;
        }
        __syncthreads();
    }

    // ---- Stage 4: Sobel/msq 1x2 -> sB[SMY][SMX] + packed NMS offsets ----
    #pragma unroll 1
    for (int s = tid; s < SMY * 33; s += NT) {
        int i = s / 33;
        int j0 = (s - i * 33) << 1;
        const ulonglong2* r0p = (const ulonglong2*)&sA[(i + 0) * SBX + j0];
        const ulonglong2* r1p = (const ulonglong2*)&sA[(i + 1) * SBX + j0];
        const ulonglong2* r2p = (const ulonglong2*)&sA[(i + 2) * SBX + j0];
        ulonglong2 r0a = r0p[0], r0b = r0p[1];
        ulonglong2 r1a = r1p[0], r1b = r1p[1];
        ulonglong2 r2a = r2p[0], r2b = r2p[1];

        int y = y0 - 1 + i;
        u64 mres[2];
        #pragma unroll
        for (int dj = 0; dj < 2; dj++) {
            u64 a00 = dj ? r0a.y : r0a.x;
            u64 a01 = dj ? r0b.x : r0a.y;
            u64 a02 = dj ? r0b.y : r0b.x;
            u64 a10 = dj ? r1a.y : r1a.x;
            u64 a12 = dj ? r1b.y : r1b.x;
            u64 a20 = dj ? r2a.y : r2a.x;
            u64 a21 = dj ? r2b.x : r2a.y;
            u64 a22 = dj ? r2b.y : r2b.x;
            u64 gx = ffma2(fsub2(a12, a10), TWO, fadd2(fsub2(a02, a00), fsub2(a22, a20)));
            u64 gy = ffma2(fsub2(a21, a01), TWO, fadd2(fsub2(a20, a00), fsub2(a22, a02)));
            int j = j0 + dj;
            int x = x0 - 1 + j;
            u64 msq = ffma2(gx, gx, fmul2(gy, gy));
            if (!((unsigned)y < H && (unsigned)x < W)) msq = 0ULL;
            mres[dj] = msq;
            if (i >= 1 && i <= TY && j >= 1 && j <= TX) {
                float gxo, gxg, gyo, gyg;
                upk(gx, gxo, gxg); upk(gy, gyo, gyg);
                int oo = axis_off(gxo, gyo);
                int og = axis_off(gxg, gyg);
                snoff[(i - 1) * TX + (j - 1)] = (short)(oo | (og << 8));
            }
        }
        *(ulonglong2*)&sB[i * SMX + j0] = make_ulonglong2(mres[0], mres[1]);
    }
    __syncthreads();

    // ---- Stage 5: NMS + threshold + XOR count ----
    int cnt = 0;
    const float* Bf = (const float*)sB;
    #pragma unroll
    for (int k = 0; k < 4; k++) {
        int px = tid + k * NT;
        int i = px >> 6, j = px & 63;
        int ci = (i + 1) * SMX + (j + 1);
        float co, cg;
        upk(sB[ci], co, cg);
        int sv = snoff[px];
        int oo = sv & 0xff;
        int og = (sv >> 8) & 0xff;
        bool eo = (co > Bf[2*(ci + oo)])     & (co > Bf[2*(ci - oo)])     & (co > TH2);
        bool eg = (cg > Bf[2*(ci + og) + 1]) & (cg > Bf[2*(ci - og) + 1]) & (cg > TH2);
        cnt += (int)(eo != eg);
    }

    // ---- block reduce + fused finalize ----
    #pragma unroll
    for (int o = 16; o > 0; o >>= 1)
        cnt += __shfl_down_sync(0xffffffffu, cnt, o);
    if ((tid & 31) == 0) wsum[tid >> 5] = cnt;
    __syncthreads();
    if (tid < (NT / 32)) {
        cnt = wsum[tid];
        #pragma unroll
        for (int o = (NT / 64); o > 0; o >>= 1)
            cnt += __shfl_down_sync(0xffffu, cnt, o);
        if (tid == 0) {
            atomicAdd(&g_count, cnt);
            __threadfence();
            int nb = gridDim.x * gridDim.y * gridDim.z;
            int t = atomicAdd(&g_ticket, 1);
            if (t == nb - 1) {
                out[0] = (float)atomicAdd(&g_count, 0) * inv_n;
                g_count = 0;
                g_ticket = 0;
            }
        }
    }
}

extern "C" void kernel_launch(void* const* d_in, const int* in_sizes, int n_in,
                              void* d_out, int out_size)
{
    const float* op = (const float*)d_in[0];
    const float* gt = (const float*)d_in[1];
    float* out = (float*)d_out;

    int batch = in_sizes[0] / (3 * HW);
    float inv_n = 1.0f / ((float)batch * HW);

    dim3 grid(W / TX, H / TY, batch);
    edge_loss_kernel<<<grid, NT>>>(op, gt, out, inv_n);
}

// round 12
// speedup vs baseline: 1.3621x; 1.0461x over previous
#include <cuda_runtime.h>
#include <math.h>

#define H 1024
#define W 1024
#define HW (H*W)
#define TX 56
#define TY 32
#define GR 40     // gray/hblur rows (TY + 8)
#define BW 60     // hblur/blurred width (TX + 4)
#define BR 36     // blurred rows (TY + 4)
#define MW 58     // msq width (TX + 2)
#define MH 34     // msq rows (TY + 2)
#define NT 512
#define NBX 19    // ceil(1024/56)

typedef unsigned long long u64;

__device__ int g_count = 0;
__device__ int g_ticket = 0;

__device__ __forceinline__ u64 pk(float lo, float hi) {
    u64 r; asm("mov.b64 %0,{%1,%2};" : "=l"(r) : "f"(lo), "f"(hi)); return r;
}
__device__ __forceinline__ void upk(u64 v, float& lo, float& hi) {
    asm("mov.b64 {%0,%1},%2;" : "=f"(lo), "=f"(hi) : "l"(v));
}
__device__ __forceinline__ u64 fadd2(u64 a, u64 b) {
    u64 r; asm("add.rn.f32x2 %0,%1,%2;" : "=l"(r) : "l"(a), "l"(b)); return r;
}
__device__ __forceinline__ u64 fmul2(u64 a, u64 b) {
    u64 r; asm("mul.rn.f32x2 %0,%1,%2;" : "=l"(r) : "l"(a), "l"(b)); return r;
}
__device__ __forceinline__ u64 ffma2(u64 a, u64 b, u64 c) {
    u64 r; asm("fma.rn.f32x2 %0,%1,%2,%3;" : "=l"(r) : "l"(a), "l"(b), "l"(c)); return r;
}
__device__ __forceinline__ u64 fneg2(u64 a) { return a ^ 0x8000000080000000ULL; }
__device__ __forceinline__ u64 fsub2(u64 a, u64 b) { return fadd2(a, fneg2(b)); }

__device__ __forceinline__ int reflecti(int c, int n) {
    if (c < 0) c = -c;
    if (c >= n) c = 2*n - 2 - c;
    return c;
}

#define GW0 0.05448868454964294f
#define GW1 0.24420134723186663f
#define GW2 0.4026199364369709f
#define T_LO 0.41421356237309503f
#define T_HI 2.414213562373095f
#define TH2  0.009999f

// NMS offset in msq (MW-wide) grid
__device__ __forceinline__ int axis_off(float gx, float gy) {
    float ax = fabsf(gx), ay = fabsf(gy);
    if (ay <= T_LO * ax) return 1;
    if (ay >= T_HI * ax) return MW;
    return ((__float_as_int(gx) ^ __float_as_int(gy)) >= 0) ? (MW - 1) : (MW + 1);
}

__device__ __forceinline__ u64 tap5(u64 t0, u64 t1, u64 t2, u64 t3, u64 t4,
                                    u64 K0, u64 K1, u64 K2) {
    u64 acc = fmul2(fadd2(t0, t4), K0);
    acc = ffma2(fadd2(t1, t3), K1, acc);
    return ffma2(t2, K2, acc);
}

__global__ __launch_bounds__(NT, 4)
void edge_loss_kernel(const float* __restrict__ op, const float* __restrict__ gt,
                      float* __restrict__ out, float inv_n)
{
    __shared__ u64   bufA[GR * BW];   // hblur -> later msq [MH][MW]
    __shared__ u64   bufB[BR * BW];   // blurred
    __shared__ short snoff[TY * TX];
    __shared__ int   wsum[NT / 32];

    const int tid  = threadIdx.x;
    const int lane = tid & 31;
    const int wid  = tid >> 5;
    const int x0 = blockIdx.x * TX;
    const int y0 = blockIdx.y * TY;
    const size_t ib = (size_t)blockIdx.z * 3 * HW;
    const float* __restrict__ opi = op + ib;
    const float* __restrict__ gti = gt + ib;

    const u64 K0 = pk(GW0, GW0), K1 = pk(GW1, GW1), K2 = pk(GW2, GW2);
    const u64 TWO = pk(2.0f, 2.0f);

    const bool xedge = (blockIdx.x == 0) || (blockIdx.x == NBX - 1);
    const int  c0  = x0 - 4 + 2 * lane;                    // gray col of this lane's first px
    const int  rc0 = reflecti(c0, W), rc1 = reflecti(c0 + 1, W);

    // ---- Stage 1+2 fused: gray (reflect) + hblur via shfl -> bufA[GR][BW] ----
    #pragma unroll 1
    for (int r = wid; r < GR; r += NT / 32) {
        int yy = reflecti(y0 - 4 + r, H);
        const float* ro = opi + yy * W;
        const float* rg = gti + yy * W;
        float ao0, ao1, ag0, ag1;
        if (!xedge) {
            float2 r_o = *(const float2*)(ro + c0);
            float2 g_o = *(const float2*)(ro + HW + c0);
            float2 b_o = *(const float2*)(ro + 2*HW + c0);
            float2 r_g = *(const float2*)(rg + c0);
            float2 g_g = *(const float2*)(rg + HW + c0);
            float2 b_g = *(const float2*)(rg + 2*HW + c0);
            ao0 = fmaf(0.299f, r_o.x, fmaf(0.587f, g_o.x, 0.114f*b_o.x));
            ao1 = fmaf(0.299f, r_o.y, fmaf(0.587f, g_o.y, 0.114f*b_o.y));
            ag0 = fmaf(0.299f, r_g.x, fmaf(0.587f, g_g.x, 0.114f*b_g.x));
            ag1 = fmaf(0.299f, r_g.y, fmaf(0.587f, g_g.y, 0.114f*b_g.y));
        } else {
            ao0 = fmaf(0.299f, ro[rc0], fmaf(0.587f, ro[HW+rc0], 0.114f*ro[2*HW+rc0]));
            ao1 = fmaf(0.299f, ro[rc1], fmaf(0.587f, ro[HW+rc1], 0.114f*ro[2*HW+rc1]));
            ag0 = fmaf(0.299f, rg[rc0], fmaf(0.587f, rg[HW+rc0], 0.114f*rg[2*HW+rc0]));
            ag1 = fmaf(0.299f, rg[rc1], fmaf(0.587f, rg[HW+rc1], 0.114f*rg[2*HW+rc1]));
        }
        u64 g0 = pk(ao0, ag0), g1 = pk(ao1, ag1);
        u64 gm0 = __shfl_up_sync(0xffffffffu, g0, 1);
        u64 gm1 = __shfl_up_sync(0xffffffffu, g1, 1);
        u64 gp0 = __shfl_down_sync(0xffffffffu, g0, 1);
        u64 gp1 = __shfl_down_sync(0xffffffffu, g1, 1);
        u64 h0 = tap5(gm0, gm1, g0, g1, gp0, K0, K1, K2);   // hblur at px 2*lane
        u64 h1 = tap5(gm1, g0, g1, gp0, gp1, K0, K1, K2);   // hblur at px 2*lane+1
        if (lane >= 1 && lane <= 30)
            *(ulonglong2*)&bufA[r * BW + 2*lane - 2] = make_ulonglong2(h0, h1);
    }
    __syncthreads();

    // ---- Stage 3: vblur 2-tall x 1-wide -> bufB[BR][BW] ----
    #pragma unroll 1
    for (int s = tid; s < (BR/2) * BW; s += NT) {
        int rg = s / BW;
        int j = s - rg * BW;
        int r0 = rg << 1;
        const u64* col = &bufA[r0 * BW + j];
        u64 t0 = col[0],      t1 = col[BW],   t2 = col[2*BW];
        u64 t3 = col[3*BW],   t4 = col[4*BW], t5 = col[5*BW];
        bufB[(r0 + 0) * BW + j] = tap5(t0, t1, t2, t3, t4, K0, K1, K2);
        bufB[(r0 + 1) * BW + j] = tap5(t1, t2, t3, t4, t5, K0, K1, K2);
    }
    __syncthreads();

    // ---- Patches: x edge-clamp then y edge-clamp of blurred field ----
    if (blockIdx.x == 0) {
        // cols -2,-1 (b=0,1) := col 0 (b=2)
        #pragma unroll 1
        for (int r = tid; r < BR; r += NT) {
            u64 v = bufB[r * BW + 2];
            bufB[r * BW + 0] = v;
            bufB[r * BW + 1] = v;
        }
        __syncthreads();
    } else if (blockIdx.x == NBX - 1) {
        // cols 1024,1025 := col 1023 ; b = col - (x0-2)
        int blast = (W - 1) - (x0 - 2);   // 17 for x0=1008
        #pragma unroll 1
        for (int r = tid; r < BR; r += NT) {
            u64 v = bufB[r * BW + blast];
            bufB[r * BW + blast + 1] = v;
            bufB[r * BW + blast + 2] = v;
        }
        __syncthreads();
    }
    if (y0 == 0) {
        #pragma unroll 1
        for (int j = tid; j < BW; j += NT) {
            u64 v = bufB[2 * BW + j];
            bufB[0 * BW + j] = v;
            bufB[1 * BW + j] = v;
        }
        __syncthreads();
    } else if (y0 == H - TY) {
        #pragma unroll 1
        for (int j = tid; j < BW; j += NT) {
            u64 v = bufB[33 * BW + j];
            bufB[34 * BW + j] = v;
            bufB[35 * BW + j] = v;
        }
        __syncthreads();
    }

    // ---- Stage 4: Sobel/msq 1x2 -> bufA[MH][MW] (overwrite) + NMS offsets ----
    // msq col m ↔ px m+3 ↔ global x0-1+m ; blurred col b ↔ px b+2
    #pragma unroll 1
    for (int s = tid; s < MH * 29; s += NT) {
        int i = s / 29;
        int cp = s - i * 29;
        int p = 3 + 2 * cp;                 // first output px (odd), 3..59
        const ulonglong2* r0p = (const ulonglong2*)&bufB[(i + 0) * BW + (p - 3)];
        const ulonglong2* r1p = (const ulonglong2*)&bufB[(i + 1) * BW + (p - 3)];
        const ulonglong2* r2p = (const ulonglong2*)&bufB[(i + 2) * BW + (p - 3)];
        ulonglong2 r0a = r0p[0], r0b = r0p[1];
        ulonglong2 r1a = r1p[0], r1b = r1p[1];
        ulonglong2 r2a = r2p[0], r2b = r2p[1];

        int y = y0 - 1 + i;
        u64 mres[2];
        #pragma unroll
        for (int dj = 0; dj < 2; dj++) {
            u64 a00 = dj ? r0a.y : r0a.x;
            u64 a01 = dj ? r0b.x : r0a.y;
            u64 a02 = dj ? r0b.y : r0b.x;
            u64 a10 = dj ? r1a.y : r1a.x;
            u64 a12 = dj ? r1b.y : r1b.x;
            u64 a20 = dj ? r2a.y : r2a.x;
            u64 a21 = dj ? r2b.x : r2a.y;
            u64 a22 = dj ? r2b.y : r2b.x;
            u64 gx = ffma2(fsub2(a12, a10), TWO, fadd2(fsub2(a02, a00), fsub2(a22, a20)));
            u64 gy = ffma2(fsub2(a21, a01), TWO, fadd2(fsub2(a20, a00), fsub2(a22, a02)));
            int px = p + dj;
            int x = x0 - 4 + px;
            u64 msq = ffma2(gx, gx, fmul2(gy, gy));
            if (!((unsigned)y < H && (unsigned)x < W)) msq = 0ULL;
            mres[dj] = msq;
            // output px range 4..59 ; i range 1..32
            if (i >= 1 && i <= TY && px >= 4 && px <= 59) {
                float gxo, gxg, gyo, gyg;
                upk(gx, gxo, gxg); upk(gy, gyo, gyg);
                int oo = axis_off(gxo, gyo);
                int og = axis_off(gxg, gyg);
                snoff[(i - 1) * TX + (px - 4)] = (short)(oo | (og << 8));
            }
        }
        *(ulonglong2*)&bufA[i * MW + (p - 3)] = make_ulonglong2(mres[0], mres[1]);
    }
    __syncthreads();

    // ---- Stage 5: NMS + threshold + XOR count ----
    int cnt = 0;
    const float* Bf = (const float*)bufA;
    #pragma unroll
    for (int k = 0; k < 4; k++) {
        int px = tid + k * NT;
        if (px < TY * TX) {
            int i = px / TX, j = px - i * TX;
            int ci = (i + 1) * MW + (j + 1);
            float co, cg;
            upk(bufA[ci], co, cg);
            int sv = snoff[px];
            int oo = sv & 0xff;
            int og = (sv >> 8) & 0xff;
            bool eo = (co > Bf[2*(ci + oo)])     & (co > Bf[2*(ci - oo)])     & (co > TH2);
            bool eg = (cg > Bf[2*(ci + og) + 1]) & (cg > Bf[2*(ci - og) + 1]) & (cg > TH2);
            cnt += (int)(eo != eg);
        }
    }

    // ---- block reduce + fused finalize ----
    #pragma unroll
    for (int o = 16; o > 0; o >>= 1)
        cnt += __shfl_down_sync(0xffffffffu, cnt, o);
    if ((tid & 31) == 0) wsum[tid >> 5] = cnt;
    __syncthreads();
    if (tid < (NT / 32)) {
        cnt = wsum[tid];
        #pragma unroll
        for (int o = (NT / 64); o > 0; o >>= 1)
            cnt += __shfl_down_sync(0xffffu, cnt, o);
        if (tid == 0) {
            atomicAdd(&g_count, cnt);
            __threadfence();
            int nb = gridDim.x * gridDim.y * gridDim.z;
            int t = atomicAdd(&g_ticket, 1);
            if (t == nb - 1) {
                out[0] = (float)atomicAdd(&g_count, 0) * inv_n;
                g_count = 0;
                g_ticket = 0;
            }
        }
    }
}

extern "C" void kernel_launch(void* const* d_in, const int* in_sizes, int n_in,
                              void* d_out, int out_size)
{
    const float* op = (const float*)d_in[0];
    const float* gt = (const float*)d_in[1];
    float* out = (float*)d_out;

    int batch = in_sizes[0] / (3 * HW);
    float inv_n = 1.0f / ((float)batch * HW);

    dim3 grid(NBX, H / TY, batch);
    edge_loss_kernel<<<grid, NT>>>(op, gt, out, inv_n);
}